// round 2
// baseline (speedup 1.0000x reference)
#include <cuda_runtime.h>
#include <cstdint>

// y[n,c,h,w] = x[n,c,h,w] * gamma[c] + beta[c]
// x: (8, 128, 256, 256) fp32. Inner spatial = 65536 elems = 16384 float4.
// In float4-index space: channel c = (i >> 14) & 127.
//
// Pure streaming kernel: 256 MiB in + 256 MiB out, zero reuse.
// Strategy: one persistent wave (148 SMs x 8 CTAs x 256 thr), grid-stride
// with 4 front-batched independent LDG.128s (MLP>=4), evict-first cache
// policy (.cs) on both load and store since nothing is re-referenced.

__global__ void __launch_bounds__(256, 8)
scale_affine_kernel(const float4* __restrict__ x,
                    const float* __restrict__ gamma,
                    const float* __restrict__ beta,
                    float4* __restrict__ y,
                    long long n4) {
    const long long tid = (long long)blockIdx.x * blockDim.x + threadIdx.x;
    const long long T   = (long long)gridDim.x * blockDim.x;

    long long i = tid;
    // Main loop: 4 independent loads in flight before any compute/store.
    for (; i + 3 * T < n4; i += 4 * T) {
        const long long i0 = i;
        const long long i1 = i + T;
        const long long i2 = i + 2 * T;
        const long long i3 = i + 3 * T;

        float4 v0 = __ldcs(&x[i0]);
        float4 v1 = __ldcs(&x[i1]);
        float4 v2 = __ldcs(&x[i2]);
        float4 v3 = __ldcs(&x[i3]);

        const int c0 = (int)((i0 >> 14) & 127);
        const int c1 = (int)((i1 >> 14) & 127);
        const int c2 = (int)((i2 >> 14) & 127);
        const int c3 = (int)((i3 >> 14) & 127);

        const float g0 = __ldg(&gamma[c0]), b0 = __ldg(&beta[c0]);
        const float g1 = __ldg(&gamma[c1]), b1 = __ldg(&beta[c1]);
        const float g2 = __ldg(&gamma[c2]), b2 = __ldg(&beta[c2]);
        const float g3 = __ldg(&gamma[c3]), b3 = __ldg(&beta[c3]);

        v0.x = fmaf(v0.x, g0, b0); v0.y = fmaf(v0.y, g0, b0);
        v0.z = fmaf(v0.z, g0, b0); v0.w = fmaf(v0.w, g0, b0);
        v1.x = fmaf(v1.x, g1, b1); v1.y = fmaf(v1.y, g1, b1);
        v1.z = fmaf(v1.z, g1, b1); v1.w = fmaf(v1.w, g1, b1);
        v2.x = fmaf(v2.x, g2, b2); v2.y = fmaf(v2.y, g2, b2);
        v2.z = fmaf(v2.z, g2, b2); v2.w = fmaf(v2.w, g2, b2);
        v3.x = fmaf(v3.x, g3, b3); v3.y = fmaf(v3.y, g3, b3);
        v3.z = fmaf(v3.z, g3, b3); v3.w = fmaf(v3.w, g3, b3);

        __stcs(&y[i0], v0);
        __stcs(&y[i1], v1);
        __stcs(&y[i2], v2);
        __stcs(&y[i3], v3);
    }
    // Tail: up to 3 more strided iterations per thread.
    for (; i < n4; i += T) {
        const int c = (int)((i >> 14) & 127);
        const float g = __ldg(&gamma[c]);
        const float b = __ldg(&beta[c]);
        float4 v = __ldcs(&x[i]);
        v.x = fmaf(v.x, g, b);
        v.y = fmaf(v.y, g, b);
        v.z = fmaf(v.z, g, b);
        v.w = fmaf(v.w, g, b);
        __stcs(&y[i], v);
    }
}

extern "C" void kernel_launch(void* const* d_in, const int* in_sizes, int n_in,
                              void* d_out, int out_size) {
    const float* x     = (const float*)d_in[0];
    const float* gamma = (const float*)d_in[1];
    const float* beta  = (const float*)d_in[2];
    float* out = (float*)d_out;

    long long n  = (long long)out_size;   // 67,108,864
    long long n4 = n >> 2;                // 16,777,216 float4

    const int threads = 256;
    const int blocks  = 148 * 8;          // exactly one resident wave

    scale_affine_kernel<<<blocks, threads>>>((const float4*)x, gamma, beta,
                                             (float4*)out, n4);
}

// round 3
// speedup vs baseline: 1.1445x; 1.1445x over previous
#include <cuda_runtime.h>
#include <cstdint>

// y[n,c,h,w] = x[n,c,h,w] * gamma[c] + beta[c]
// x: (8, 128, 256, 256) fp32 = 67,108,864 elems = 16,777,216 float4.
// Inner spatial = 256*256 = 65536 elems = 16384 float4 per channel.
//
// Flat launch: one float4 per thread, 65536 blocks x 256 threads.
// Each block covers 1024 contiguous float4 = 1/16 of one channel, so the
// channel index is uniform per block: c = (blockIdx.x >> 4) & 127.
// Hot path per thread: LDG.128 -> 4x FFMA -> STG.128. Pure stream.

__global__ void __launch_bounds__(256)
scale_affine_flat(const float4* __restrict__ x,
                  const float* __restrict__ gamma,
                  const float* __restrict__ beta,
                  float4* __restrict__ y) {
    const unsigned i = blockIdx.x * 256u + threadIdx.x;   // float4 index
    const int c = (int)((blockIdx.x >> 4) & 127u);        // uniform per block

    const float g = __ldg(&gamma[c]);
    const float b = __ldg(&beta[c]);

    float4 v = x[i];
    v.x = fmaf(v.x, g, b);
    v.y = fmaf(v.y, g, b);
    v.z = fmaf(v.z, g, b);
    v.w = fmaf(v.w, g, b);
    y[i] = v;
}

extern "C" void kernel_launch(void* const* d_in, const int* in_sizes, int n_in,
                              void* d_out, int out_size) {
    const float* x     = (const float*)d_in[0];
    const float* gamma = (const float*)d_in[1];
    const float* beta  = (const float*)d_in[2];
    float* out = (float*)d_out;

    // out_size = 67,108,864 -> n4 = 16,777,216 -> 65536 blocks of 256.
    const unsigned n4 = (unsigned)(out_size >> 2);
    const unsigned blocks = n4 / 256u;

    scale_affine_flat<<<blocks, 256>>>((const float4*)x, gamma, beta,
                                       (float4*)out);
}

// round 5
// speedup vs baseline: 1.1498x; 1.0047x over previous
#include <cuda_runtime.h>
#include <cstdint>

// y[n,c,h,w] = x[n,c,h,w] * gamma[c] + beta[c]
// x: (8, 128, 256, 256) fp32 = 16,777,216 float4. Channel = 16384 float4.
//
// Flat launch, 2 float4 per thread: 32768 blocks x 256 threads.
// Block covers 512 contiguous float4 (256 at base, 256 at base+256).
// 16384/512 = 32 blocks per channel -> c = (blockIdx.x >> 5) & 127 (uniform).
// Two independent LDG.128s front-batched (MLP=2) before any FFMA/STG.

__global__ void __launch_bounds__(256)
scale_affine_flat2(const float4* __restrict__ x,
                   const float* __restrict__ gamma,
                   const float* __restrict__ beta,
                   float4* __restrict__ y) {
    const unsigned base = blockIdx.x * 512u + threadIdx.x;  // float4 index
    const unsigned i0 = base;
    const unsigned i1 = base + 256u;
    const int c = (int)((blockIdx.x >> 5) & 127u);          // uniform per block

    // Front-batch both loads.
    float4 v0 = x[i0];
    float4 v1 = x[i1];

    const float g = __ldg(&gamma[c]);
    const float b = __ldg(&beta[c]);

    v0.x = fmaf(v0.x, g, b);
    v0.y = fmaf(v0.y, g, b);
    v0.z = fmaf(v0.z, g, b);
    v0.w = fmaf(v0.w, g, b);
    v1.x = fmaf(v1.x, g, b);
    v1.y = fmaf(v1.y, g, b);
    v1.z = fmaf(v1.z, g, b);
    v1.w = fmaf(v1.w, g, b);

    y[i0] = v0;
    y[i1] = v1;
}

extern "C" void kernel_launch(void* const* d_in, const int* in_sizes, int n_in,
                              void* d_out, int out_size) {
    const float* x     = (const float*)d_in[0];
    const float* gamma = (const float*)d_in[1];
    const float* beta  = (const float*)d_in[2];
    float* out = (float*)d_out;

    // out_size = 67,108,864 -> n4 = 16,777,216 -> 32768 blocks of 256, 2 f4/thread.
    const unsigned n4 = (unsigned)(out_size >> 2);
    const unsigned blocks = n4 / 512u;

    scale_affine_flat2<<<blocks, 256>>>((const float4*)x, gamma, beta,
                                        (float4*)out);
}

// round 6
// speedup vs baseline: 1.1503x; 1.0004x over previous
#include <cuda_runtime.h>
#include <cstdint>

// y[n,c,h,w] = x[n,c,h,w] * gamma[c] + beta[c]
// x: (8, 128, 256, 256) fp32 = 16,777,216 float4. Channel = 16384 float4.
//
// Flat launch, 4 float4 per thread: 16384 blocks x 256 threads.
// Block covers 1024 contiguous float4 (4 slabs of 256).
// 16384/1024 = 16 blocks per channel -> c = (blockIdx.x >> 4) & 127 (uniform).
// Four independent LDG.128s front-batched (MLP=4) before any FFMA/STG.

__global__ void __launch_bounds__(256)
scale_affine_flat4(const float4* __restrict__ x,
                   const float* __restrict__ gamma,
                   const float* __restrict__ beta,
                   float4* __restrict__ y) {
    const unsigned base = blockIdx.x * 1024u + threadIdx.x;  // float4 index
    const unsigned i0 = base;
    const unsigned i1 = base + 256u;
    const unsigned i2 = base + 512u;
    const unsigned i3 = base + 768u;
    const int c = (int)((blockIdx.x >> 4) & 127u);           // uniform per block

    // Front-batch all four loads.
    float4 v0 = x[i0];
    float4 v1 = x[i1];
    float4 v2 = x[i2];
    float4 v3 = x[i3];

    const float g = __ldg(&gamma[c]);
    const float b = __ldg(&beta[c]);

    v0.x = fmaf(v0.x, g, b); v0.y = fmaf(v0.y, g, b);
    v0.z = fmaf(v0.z, g, b); v0.w = fmaf(v0.w, g, b);
    v1.x = fmaf(v1.x, g, b); v1.y = fmaf(v1.y, g, b);
    v1.z = fmaf(v1.z, g, b); v1.w = fmaf(v1.w, g, b);
    v2.x = fmaf(v2.x, g, b); v2.y = fmaf(v2.y, g, b);
    v2.z = fmaf(v2.z, g, b); v2.w = fmaf(v2.w, g, b);
    v3.x = fmaf(v3.x, g, b); v3.y = fmaf(v3.y, g, b);
    v3.z = fmaf(v3.z, g, b); v3.w = fmaf(v3.w, g, b);

    y[i0] = v0;
    y[i1] = v1;
    y[i2] = v2;
    y[i3] = v3;
}

extern "C" void kernel_launch(void* const* d_in, const int* in_sizes, int n_in,
                              void* d_out, int out_size) {
    const float* x     = (const float*)d_in[0];
    const float* gamma = (const float*)d_in[1];
    const float* beta  = (const float*)d_in[2];
    float* out = (float*)d_out;

    // out_size = 67,108,864 -> n4 = 16,777,216 -> 16384 blocks of 256, 4 f4/thread.
    const unsigned n4 = (unsigned)(out_size >> 2);
    const unsigned blocks = n4 / 1024u;

    scale_affine_flat4<<<blocks, 256>>>((const float4*)x, gamma, beta,
                                        (float4*)out);
}